// round 16
// baseline (speedup 1.0000x reference)
#include <cuda_runtime.h>

#define OUT_H      8
#define MAX_WIDTH  384
#define NSTRIP     2048          // NUM_BOXES * OUT_H
#define FH         160
#define FW         160
#define CCH        32
#define NUM_BOXES  256

// 8 threads per pixel (one float4 each -> 128B-contiguous gathers/stores).
// Each thread handles 4 CONSECUTIVE columns; a block covers one 128-column
// band of one strip (3 bands per strip). Blocks whose whole band is beyond
// the box width store zeros and exit (~1/3 of blocks on average). Strips are
// permuted across blocks so early-exit blocks are evenly mixed over SMs.

__global__ __launch_bounds__(256)
void rotate_bilinear_kernel(const float* __restrict__ feat,
                            const float* __restrict__ theta,
                            const int*   __restrict__ box_info,
                            float4*      __restrict__ out)
{
    // 6144 blocks = 2048 strips x 3 bands of 128 columns.
    const int s_raw = blockIdx.x & (NSTRIP - 1);          // 0..2047
    const int g     = blockIdx.x >> 11;                   // 0..2 (band)
    const int t     = (s_raw * 331) & (NSTRIP - 1);       // permuted strip

    const int c4   = threadIdx.x & 7;                     // float4 slot in 32 ch
    const int q    = threadIdx.x >> 3;                    // 0..31 colslot
    const int col0 = g * 128 + q * 4;                     // first of 4 consecutive cols

    const int row = t & (OUT_H - 1);
    const int b   = t >> 3;

    const int bw = __ldg(&box_info[2 * b + 1]);

    // Output base; this thread's pixels step by (CCH/4)
    float4* __restrict__ op = out + ((long)t * MAX_WIDTH + col0) * (CCH / 4) + c4;

    // ---- block-level early exit: whole band beyond box width ----
    if (g * 128 >= bw) {
        const float4 z = make_float4(0.f, 0.f, 0.f, 0.f);
        __stcs(op,                  z);
        __stcs(op + 1 * (CCH / 4), z);
        __stcs(op + 2 * (CCH / 4), z);
        __stcs(op + 3 * (CCH / 4), z);
        return;
    }

    const int img = __ldg(&box_info[2 * b]);
    const float* th = theta + 6 * b;
    const float t0 = __ldg(th + 0), t1 = __ldg(th + 1), t2 = __ldg(th + 2);
    const float t3 = __ldg(th + 3), t4 = __ldg(th + 4), t5 = __ldg(th + 5);

    const float rcp2 = __fdividef(2.0f, (float)bw - 1.0f);
    const float yt   = -1.0f + 2.0f * (float)row * (1.0f / (float)(OUT_H - 1));

    // Folded transform: x = Ax*col + Bx, y = Ay*col + By
    const float Ax = t0 * rcp2 * ((float)FW * 0.5f);
    const float Bx = (t1 * yt + t2 - t0 + 1.0f) * ((float)FW * 0.5f);
    const float Ay = t3 * rcp2 * ((float)FH * 0.5f);
    const float By = (t4 * yt + t5 - t3 + 1.0f) * ((float)FH * 0.5f);

    // Feature base with image and channel-slot folded in (float4 units)
    const float4* __restrict__ fb =
        (const float4*)feat + (long)img * (FH * FW * (CCH / 4)) + c4;

    #pragma unroll
    for (int k = 0; k < 4; ++k) {
        const int pc = col0 + k;
        float4 o = make_float4(0.f, 0.f, 0.f, 0.f);

        if (pc < bw) {
            const float pf = (float)pc;
            const float x  = fmaf(Ax, pf, Bx);
            const float y  = fmaf(Ay, pf, By);

            const int x0i = __float2int_rd(x);
            const int y0i = __float2int_rd(y);
            const int x0c = min(max(x0i,     0), FW - 1);
            const int x1c = min(max(x0i + 1, 0), FW - 1);
            const int y0c = min(max(y0i,     0), FH - 1);
            const int y1c = min(max(y0i + 1, 0), FH - 1);

            const float dx0 = (float)x1c - x, dx1 = x - (float)x0c;
            const float dy0 = (float)y1c - y, dy1 = y - (float)y0c;
            const float wa = dx0 * dy0, wb = dx0 * dy1;
            const float wc = dx1 * dy0, wd = dx1 * dy1;

            const int ry0 = y0c * (FW * (CCH / 4));
            const int ry1 = y1c * (FW * (CCH / 4));
            const int cx0 = x0c * (CCH / 4);
            const int cx1 = x1c * (CCH / 4);

            const float4 Ia = __ldg(fb + (ry0 + cx0));
            const float4 Ib = __ldg(fb + (ry1 + cx0));
            const float4 Ic = __ldg(fb + (ry0 + cx1));
            const float4 Id = __ldg(fb + (ry1 + cx1));

            o.x = wa * Ia.x + wb * Ib.x + wc * Ic.x + wd * Id.x;
            o.y = wa * Ia.y + wb * Ib.y + wc * Ic.y + wd * Id.y;
            o.z = wa * Ia.z + wb * Ib.z + wc * Ic.z + wd * Id.z;
            o.w = wa * Ia.w + wb * Ib.w + wc * Ic.w + wd * Id.w;
        }

        __stcs(op + k * (CCH / 4), o);
    }
}

extern "C" void kernel_launch(void* const* d_in, const int* in_sizes, int n_in,
                              void* d_out, int out_size)
{
    const float* feat  = (const float*)d_in[0];   // [8,160,160,32] f32
    const float* theta = (const float*)d_in[1];   // [256,6] f32
    const int*   binfo = (const int*)d_in[2];     // [256,2] i32

    const int grid = NSTRIP * 3;                  // 6144 blocks of 256
    rotate_bilinear_kernel<<<grid, 256>>>(feat, theta, binfo, (float4*)d_out);
}

// round 17
// speedup vs baseline: 1.0653x; 1.0653x over previous
#include <cuda_runtime.h>

#define OUT_H      8
#define MAX_WIDTH  384
#define QW         96            // MAX_WIDTH / 4 : column stride between a thread's pixels
#define FH         160
#define FW         160
#define CCH        32
#define NUM_BOXES  256

// Champion (R5) layout: 8 threads per pixel (one float4 each -> 128B
// contiguous gathers/stores), 4 pixels per thread at cols c + k*96,
// 256-thread blocks, grid 6144. Single change vs R5: image index and
// channel slot folded once into a base pointer (fewer ALU ops per pixel).

__global__ __launch_bounds__(256)
void rotate_bilinear_kernel(const float* __restrict__ feat,
                            const float* __restrict__ theta,
                            const int*   __restrict__ box_info,
                            float4*      __restrict__ out)
{
    const int tid = blockIdx.x * blockDim.x + threadIdx.x;

    const int c4  = tid & 7;          // float4 slot within 32 channels
    const int p   = tid >> 3;         // (box, row, col-slot)
    const int col = p % QW;           // base column; pixels at col + k*96
    const int t   = p / QW;           // strip = b*OUT_H + row
    const int row = t & (OUT_H - 1);
    const int b   = t >> 3;           // OUT_H == 8

    const int img = __ldg(&box_info[2 * b]);
    const int bw  = __ldg(&box_info[2 * b + 1]);

    const float* th = theta + 6 * b;
    const float t0 = __ldg(th + 0), t1 = __ldg(th + 1), t2 = __ldg(th + 2);
    const float t3 = __ldg(th + 3), t4 = __ldg(th + 4), t5 = __ldg(th + 5);

    const float rcp2 = __fdividef(2.0f, (float)bw - 1.0f);
    const float yt   = -1.0f + 2.0f * (float)row * (1.0f / (float)(OUT_H - 1));

    // Folded transform: x = Ax*col + Bx, y = Ay*col + By
    const float Ax = t0 * rcp2 * ((float)FW * 0.5f);
    const float Bx = (t1 * yt + t2 - t0 + 1.0f) * ((float)FW * 0.5f);
    const float Ay = t3 * rcp2 * ((float)FH * 0.5f);
    const float By = (t4 * yt + t5 - t3 + 1.0f) * ((float)FH * 0.5f);

    // Feature base with image and channel-slot folded in (float4 units)
    const float4* __restrict__ fb =
        (const float4*)feat + (long)img * (FH * FW * (CCH / 4)) + c4;

    // Output base; pixels step by QW*(CCH/4)
    float4* __restrict__ op = out + ((long)t * MAX_WIDTH + col) * (CCH / 4) + c4;

    #pragma unroll
    for (int k = 0; k < 4; ++k) {
        const int pc = col + k * QW;
        float4 o = make_float4(0.f, 0.f, 0.f, 0.f);

        if (pc < bw) {
            const float pf = (float)pc;
            const float x  = fmaf(Ax, pf, Bx);
            const float y  = fmaf(Ay, pf, By);

            const int x0i = __float2int_rd(x);
            const int y0i = __float2int_rd(y);
            const int x0c = min(max(x0i,     0), FW - 1);
            const int x1c = min(max(x0i + 1, 0), FW - 1);
            const int y0c = min(max(y0i,     0), FH - 1);
            const int y1c = min(max(y0i + 1, 0), FH - 1);

            const float dx0 = (float)x1c - x, dx1 = x - (float)x0c;
            const float dy0 = (float)y1c - y, dy1 = y - (float)y0c;
            const float wa = dx0 * dy0, wb = dx0 * dy1;
            const float wc = dx1 * dy0, wd = dx1 * dy1;

            const int ry0 = y0c * (FW * (CCH / 4));
            const int ry1 = y1c * (FW * (CCH / 4));
            const int cx0 = x0c * (CCH / 4);
            const int cx1 = x1c * (CCH / 4);

            const float4 Ia = __ldg(fb + (ry0 + cx0));
            const float4 Ib = __ldg(fb + (ry1 + cx0));
            const float4 Ic = __ldg(fb + (ry0 + cx1));
            const float4 Id = __ldg(fb + (ry1 + cx1));

            o.x = wa * Ia.x + wb * Ib.x + wc * Ic.x + wd * Id.x;
            o.y = wa * Ia.y + wb * Ib.y + wc * Ic.y + wd * Id.y;
            o.z = wa * Ia.z + wb * Ib.z + wc * Ic.z + wd * Id.z;
            o.w = wa * Ia.w + wb * Ib.w + wc * Ic.w + wd * Id.w;
        }

        __stcs(op + k * (QW * (CCH / 4)), o);
    }
}

extern "C" void kernel_launch(void* const* d_in, const int* in_sizes, int n_in,
                              void* d_out, int out_size)
{
    const float* feat  = (const float*)d_in[0];   // [8,160,160,32] f32
    const float* theta = (const float*)d_in[1];   // [256,6] f32
    const int*   binfo = (const int*)d_in[2];     // [256,2] i32

    const int total_threads = NUM_BOXES * OUT_H * QW * 8; // 1,572,864
    const int block = 256;
    const int grid  = total_threads / block;      // 6144

    rotate_bilinear_kernel<<<grid, block>>>(feat, theta, binfo, (float4*)d_out);
}